// round 15
// baseline (speedup 1.0000x reference)
#include <cuda_runtime.h>
#include <cuda_bf16.h>
#include <mma.h>
#include <cstdint>

using namespace nvcuda;

#define NA      8192
#define DD      128
#define HH      256
#define NC1     12          // cells per dimension (box 60 A / cutoff 5 A)
#define NCELL   (NC1*NC1*NC1)
#define MAXC    320         // max candidate atoms across 27 cells (mean ~128)
#define BMT     64          // mlp block tile M
#define BNT     64          // mlp block tile N
#define NBLK    ((NA/BMT)*(HH/BNT))   // 512 mlp blocks
#define LDS_AB  72          // padded smem leading dim (bf16)
#define LDS_AC  68          // padded epilogue leading dim (f32)

#define ABYTES   (64 * LDS_AB * 2)        // 9216 B per staged array
#define BUFBYTES (4 * ABYTES)             // 36864 B per kc buffer
#define SMEM_MLP (2 * BUFBYTES + 512 + 16)

typedef unsigned long long u64;

#define CP_ASYNC16(dst_u32, src_ptr) \
    asm volatile("cp.async.cg.shared.global [%0], [%1], 16;" \
                 :: "r"(dst_u32), "l"(src_ptr))
#define CP_COMMIT()  asm volatile("cp.async.commit_group;")
#define CP_WAIT0()   asm volatile("cp.async.wait_group 0;")

// ---- Scratch (static __device__ — no allocation) ---------------------------
__device__ float4        g_pos4[NA];
__device__ int           g_cellid[NA];
__device__ int           g_start[NCELL + 1];
__device__ int           g_slot[NA];       // cell-sorted original atom indices
__device__ float4        g_spos[NA];       // cell-sorted positions
__device__ int           g_stype[NA];      // cell-sorted types
__device__ __nv_bfloat16 g_Ahi[NA * HH];   // feat hi, row-major [8192][256]
__device__ __nv_bfloat16 g_Alo[NA * HH];   // feat lo
__device__ __nv_bfloat16 g_Bhi[HH * HH];   // W1 hi,  row-major [256][256]
__device__ __nv_bfloat16 g_Blo[HH * HH];   // W1 lo
__device__ float         g_partial[NBLK];
__device__ int           g_done = 0;

// bf16 two-term split: v ~= hi + lo, each bf16 (lo = rounding residual)
__device__ __forceinline__ void bf16_split(float v, __nv_bfloat16& h,
                                           __nv_bfloat16& l) {
    h = __float2bfloat16(v);
    l = __float2bfloat16(__fadd_rn(v, -__bfloat162float(h)));
}

__device__ __forceinline__ void store_split4(__nv_bfloat16* hi,
                                             __nv_bfloat16* lo, float4 v) {
    __nv_bfloat162 h01, h23, l01, l23;
    __nv_bfloat16 h, l;
    bf16_split(v.x, h, l); h01.x = h; l01.x = l;
    bf16_split(v.y, h, l); h01.y = h; l01.y = l;
    bf16_split(v.z, h, l); h23.x = h; l23.x = l;
    bf16_split(v.w, h, l); h23.y = h; l23.y = l;
    ((__nv_bfloat162*)hi)[0] = h01;
    ((__nv_bfloat162*)hi)[1] = h23;
    ((__nv_bfloat162*)lo)[0] = l01;
    ((__nv_bfloat162*)lo)[1] = l23;
}

// ---------------------------------------------------------------------------
// W1 bf16 split, row-major [K][N].
// ---------------------------------------------------------------------------
__global__ void k_wsplit(const float* __restrict__ W1) {
    int idx = blockIdx.x * 256 + threadIdx.x;     // 65536 total
    __nv_bfloat16 h, l;
    bf16_split(W1[idx], h, l);
    g_Bhi[idx] = h;
    g_Blo[idx] = l;
}

// ---------------------------------------------------------------------------
// Prep: nm -> angstrom; s = ((x*x)+(y*y))+(z*z) with NO fma contraction
// (matches XLA's elementwise/reduce rounding). Cell id only.
// ---------------------------------------------------------------------------
__global__ void k_prep(const float* __restrict__ pos) {
    int i = blockIdx.x * 256 + threadIdx.x;
    if (i < NA) {
        float x = __fmul_rn(10.0f, pos[3 * i + 0]);
        float y = __fmul_rn(10.0f, pos[3 * i + 1]);
        float z = __fmul_rn(10.0f, pos[3 * i + 2]);
        float s = __fadd_rn(__fadd_rn(__fmul_rn(x, x), __fmul_rn(y, y)),
                            __fmul_rn(z, z));
        g_pos4[i] = make_float4(x, y, z, s);
        int cx = min(NC1 - 1, max(0, (int)(x * 0.2f)));
        int cy = min(NC1 - 1, max(0, (int)(y * 0.2f)));
        int cz = min(NC1 - 1, max(0, (int)(z * 0.2f)));
        g_cellid[i] = (cz * NC1 + cy) * NC1 + cx;
    }
}

// ---------------------------------------------------------------------------
// Fused histogram + scan + scatter: one single-block kernel with SMEM
// counts/cursors (smem atomics ~32cyc vs ATOMG ~318cyc, no launch gaps).
// ---------------------------------------------------------------------------
__global__ void __launch_bounds__(1024) k_scan_scatter() {
    __shared__ int cnt[NCELL];
    __shared__ int cur[NCELL];
    __shared__ int a[2048], b[2048];
    const int t = threadIdx.x;

    cnt[t] = 0;
    if (t < NCELL - 1024) cnt[1024 + t] = 0;
    __syncthreads();

    int myc[8];
    #pragma unroll
    for (int k = 0; k < 8; k++) {
        myc[k] = g_cellid[t * 8 + k];
        atomicAdd(&cnt[myc[k]], 1);
    }
    __syncthreads();

    #pragma unroll
    for (int k = 0; k < 2; k++) {
        int idx = t + 1024 * k;
        a[idx] = (idx < NCELL) ? cnt[idx] : 0;
    }
    __syncthreads();
    int* src = a; int* dst = b;
    for (int s = 1; s < 2048; s <<= 1) {
        #pragma unroll
        for (int k = 0; k < 2; k++) {
            int idx = t + 1024 * k;
            int v = src[idx];
            if (idx >= s) v += src[idx - s];
            dst[idx] = v;
        }
        __syncthreads();
        int* tmp = src; src = dst; dst = tmp;
    }
    #pragma unroll
    for (int k = 0; k < 2; k++) {
        int idx = t + 1024 * k;
        if (idx < NCELL) {
            int st = src[idx] - cnt[idx];
            g_start[idx] = st;
            cur[idx]     = st;
        }
    }
    if (t == 0) g_start[NCELL] = NA;
    __syncthreads();

    #pragma unroll
    for (int k = 0; k < 8; k++) {
        int slot = atomicAdd(&cur[myc[k]], 1);
        g_slot[slot] = t * 8 + k;   // order arbitrary; k_sort restores
    }
}

// ---------------------------------------------------------------------------
// Per-cell register sort of g_slot (ascending -> deterministic order).
// 1728 threads spread over 54 blocks (54 SMs) — loads are independent.
// ---------------------------------------------------------------------------
__global__ void k_sort() {
    int c = blockIdx.x * 32 + threadIdx.x;
    if (c < NCELL) {
        int st = g_start[c];
        int cn = g_start[c + 1] - st;
        if (cn > 32) cn = 32;                    // statistically unreachable
        int loc[32];
        for (int i = 0; i < cn; i++) loc[i] = g_slot[st + i];
        for (int i = 1; i < cn; i++) {
            int v = loc[i], j = i - 1;
            while (j >= 0 && loc[j] > v) { loc[j + 1] = loc[j]; j--; }
            loc[j + 1] = v;
        }
        for (int i = 0; i < cn; i++) g_slot[st + i] = loc[i];
    }
}

// ---------------------------------------------------------------------------
// Slot-parallel gather: 8192 independent chains across 32 blocks.
// ---------------------------------------------------------------------------
__global__ void k_gather(const int* __restrict__ types) {
    int i = blockIdx.x * 256 + threadIdx.x;
    if (i < NA) {
        int a = g_slot[i];
        g_spos[i]  = g_pos4[a];
        g_stype[i] = types[a];
    }
}

// ---------------------------------------------------------------------------
// Per-CELL radius graph + aggregation, warp-independent home atoms.
// d2 <= 25.01f prefilter (provably includes all reference-acceptable pairs;
// exact test still applied inside). Pair math bit-exact vs reference:
//   dot = fma(z,z, fma(y,y, x*x));  d2 = RN(RN(s_i+s_j) - 2*dot)
// ---------------------------------------------------------------------------
__global__ void __launch_bounds__(128) k_agg(const float* __restrict__ emb) {
    __shared__ float4        s_cpos[MAXC];
    __shared__ int           s_ctyp[MAXC];
    __shared__ unsigned char s_cmap[MAXC];
    __shared__ int           s_gst[32];
    __shared__ int           s_coff[33];

    const int tl   = threadIdx.x;
    const int lane = tl & 31, w = tl >> 5;
    const int c  = blockIdx.x;
    const int cx = c % NC1, cy = (c / NC1) % NC1, cz = c / (NC1 * NC1);

    if (tl < 32) {
        int st = 0, cnt = 0;
        if (tl < 27) {
            int nx = cx + tl % 3 - 1;
            int ny = cy + (tl / 3) % 3 - 1;
            int nz = cz + tl / 9 - 1;
            if (nx >= 0 && nx < NC1 && ny >= 0 && ny < NC1 &&
                nz >= 0 && nz < NC1) {
                int nc = (nz * NC1 + ny) * NC1 + nx;
                st  = g_start[nc];
                cnt = g_start[nc + 1] - st;
            }
        }
        s_gst[tl] = st;
        int v = cnt;
        #pragma unroll
        for (int o = 1; o < 32; o <<= 1) {
            int u2 = __shfl_up_sync(0xffffffffu, v, o);
            if (lane >= o) v += u2;
        }
        s_coff[tl + 1] = v;
        if (tl == 0) s_coff[0] = 0;
        int off = v - cnt;
        for (int q = 0; q < cnt; q++)
            s_cmap[off + q] = (unsigned char)tl;
    }
    __syncthreads();

    const int ncand = s_coff[27];
    const int hbase = s_coff[13];
    const int nhome = s_coff[14] - s_coff[13];
    const int hst   = s_gst[13];
    if (nhome == 0) return;

    for (int p = tl; p < ncand; p += 128) {
        int q    = s_cmap[p];
        int slot = s_gst[q] + (p - s_coff[q]);
        s_cpos[p] = g_spos[slot];
        s_ctyp[p] = g_stype[slot];
    }
    __syncthreads();

    for (int ha = w; ha < nhome; ha += 4) {
        const float4 pi = s_cpos[hbase + ha];
        float4 acc = make_float4(0.f, 0.f, 0.f, 0.f);

        for (int base = 0; base < ncand; base += 32) {
            int k = base + lane;
            int pred = 0, typ = 0;
            float phi = 0.0f;
            if (k < ncand) {
                float4 pj = s_cpos[k];
                float dot = __fmul_rn(pi.x, pj.x);
                dot = fmaf(pi.y, pj.y, dot);
                dot = fmaf(pi.z, pj.z, dot);
                float t1 = __fadd_rn(pi.w, pj.w);
                float d2 = __fadd_rn(t1, __fmul_rn(-2.0f, dot));
                if (d2 > 1e-12f && d2 <= 25.01f) {       // cheap prefilter
                    float d = __fsqrt_rn(d2);
                    if (d <= 5.0f) {                      // exact ref test
                        pred = 1; phi = expf(-d); typ = s_ctyp[k];
                    }
                }
            }
            unsigned m = __ballot_sync(0xffffffffu, pred);
            while (m) {                          // ascending lane = cand order
                int srcl = __ffs(m) - 1;
                m &= m - 1;
                float ph = __shfl_sync(0xffffffffu, phi, srcl);
                int   ty = __shfl_sync(0xffffffffu, typ, srcl);
                float4 ev = *(const float4*)(emb + ty * DD + lane * 4);
                acc.x = fmaf(ph, ev.x, acc.x);
                acc.y = fmaf(ph, ev.y, acc.y);
                acc.z = fmaf(ph, ev.z, acc.z);
                acc.w = fmaf(ph, ev.w, acc.w);
            }
        }

        const int i  = g_slot[hst + ha];         // original atom index
        const int ti = s_ctyp[hbase + ha];
        float4 hv = *(const float4*)(emb + ti * DD + lane * 4);
        store_split4(g_Ahi + (u64)i * HH + lane * 4,
                     g_Alo + (u64)i * HH + lane * 4, hv);
        store_split4(g_Ahi + (u64)i * HH + 128 + lane * 4,
                     g_Alo + (u64)i * HH + 128 + lane * 4, acc);
    }
}

// ---------------------------------------------------------------------------
// MLP on wmma bf16 two-term split GEMM, cp.async double-buffered staging
// (unchanged from round 13 — known good).
// ---------------------------------------------------------------------------
__global__ void __launch_bounds__(128) k_mlp(const float* __restrict__ w2,
                                             float* __restrict__ out) {
    extern __shared__ __align__(16) char smem_dyn[];
    float* s_acc  = (float*)smem_dyn;             // reused after mainloop
    float* s_red  = (float*)(smem_dyn + 2 * BUFBYTES);
    int*   s_last = (int*)(smem_dyn + 2 * BUFBYTES + 512);

    const int tid  = threadIdx.x;
    const int wid  = tid >> 5;
    const int wm   = wid & 1, wn = wid >> 1;
    const int mt   = blockIdx.x >> 2, nt = blockIdx.x & 3;
    const int m0   = mt * BMT, n0 = nt * BNT;

    uint32_t sb;
    asm("{ .reg .u64 t; cvta.to.shared.u64 t, %1; cvt.u32.u64 %0, t; }"
        : "=r"(sb) : "l"(smem_dyn));

    auto stage = [&](int kc, int buf) {
        uint32_t dbase = sb + buf * BUFBYTES;
        #pragma unroll
        for (int q = 0; q < 4; q++) {
            int j = tid + 128 * q;
            int row = j >> 3, c8 = j & 7;
            uint32_t doff = dbase + row * (LDS_AB * 2) + c8 * 16;
            const char* sa = (const char*)(g_Ahi + (u64)(m0 + row) * HH + kc * 64) + c8 * 16;
            const char* sl = (const char*)(g_Alo + (u64)(m0 + row) * HH + kc * 64) + c8 * 16;
            const char* sh = (const char*)(g_Bhi + (u64)(kc * 64 + row) * HH + n0) + c8 * 16;
            const char* sw = (const char*)(g_Blo + (u64)(kc * 64 + row) * HH + n0) + c8 * 16;
            CP_ASYNC16(doff + 0 * ABYTES, sa);
            CP_ASYNC16(doff + 1 * ABYTES, sl);
            CP_ASYNC16(doff + 2 * ABYTES, sh);
            CP_ASYNC16(doff + 3 * ABYTES, sw);
        }
        CP_COMMIT();
    };

    wmma::fragment<wmma::accumulator, 16, 16, 16, float> acc[2][2];
    #pragma unroll
    for (int i = 0; i < 2; i++)
        #pragma unroll
        for (int j = 0; j < 2; j++)
            wmma::fill_fragment(acc[i][j], 0.0f);

    stage(0, 0);

    #pragma unroll 1
    for (int kc = 0; kc < 4; kc++) {
        CP_WAIT0();
        __syncthreads();                 // data landed; prior buf free
        if (kc < 3) stage(kc + 1, (kc + 1) & 1);

        const char* bufp = smem_dyn + (kc & 1) * BUFBYTES;
        const __nv_bfloat16* sAhi = (const __nv_bfloat16*)(bufp + 0 * ABYTES);
        const __nv_bfloat16* sAlo = (const __nv_bfloat16*)(bufp + 1 * ABYTES);
        const __nv_bfloat16* sBhi = (const __nv_bfloat16*)(bufp + 2 * ABYTES);
        const __nv_bfloat16* sBlo = (const __nv_bfloat16*)(bufp + 3 * ABYTES);

        #pragma unroll
        for (int sp = 0; sp < 3; sp++) {          // hi*hi, hi*lo, lo*hi
            const __nv_bfloat16* sA = (sp == 2) ? sAlo : sAhi;
            const __nv_bfloat16* sB = (sp == 1) ? sBlo : sBhi;
            #pragma unroll
            for (int ks = 0; ks < 4; ks++) {
                wmma::fragment<wmma::matrix_a, 16, 16, 16, __nv_bfloat16,
                               wmma::row_major> af[2];
                wmma::fragment<wmma::matrix_b, 16, 16, 16, __nv_bfloat16,
                               wmma::row_major> bf[2];
                #pragma unroll
                for (int i = 0; i < 2; i++)
                    wmma::load_matrix_sync(
                        af[i], sA + (wm * 32 + i * 16) * LDS_AB + ks * 16,
                        LDS_AB);
                #pragma unroll
                for (int j = 0; j < 2; j++)
                    wmma::load_matrix_sync(
                        bf[j], sB + (ks * 16) * LDS_AB + wn * 32 + j * 16,
                        LDS_AB);
                #pragma unroll
                for (int i = 0; i < 2; i++)
                    #pragma unroll
                    for (int j = 0; j < 2; j++)
                        wmma::mma_sync(acc[i][j], af[i], bf[j], acc[i][j]);
            }
        }
    }
    __syncthreads();

    #pragma unroll
    for (int i = 0; i < 2; i++)
        #pragma unroll
        for (int j = 0; j < 2; j++)
            wmma::store_matrix_sync(
                s_acc + (wm * 32 + i * 16) * LDS_AC + wn * 32 + j * 16,
                acc[i][j], LDS_AC, wmma::mem_row_major);
    __syncthreads();

    float p = 0.0f;
    #pragma unroll
    for (int e = 0; e < 32; e++) {
        int idx = tid + 128 * e;
        int row = idx >> 6, col = idx & 63;
        p += fmaxf(s_acc[row * LDS_AC + col], 0.0f) * __ldg(w2 + n0 + col);
    }
    s_red[tid] = p;
    __syncthreads();
    for (int s = 64; s > 0; s >>= 1) {
        if (tid < s) s_red[tid] += s_red[tid + s];
        __syncthreads();
    }
    if (tid == 0) g_partial[blockIdx.x] = s_red[0];

    __threadfence();
    if (tid == 0) *s_last = (atomicAdd(&g_done, 1) == gridDim.x - 1);
    __syncthreads();
    if (*s_last) {
        __threadfence();
        volatile float* gp = (volatile float*)g_partial;
        float q = 0.0f;
        #pragma unroll
        for (int e = 0; e < 4; e++) q += gp[tid + 128 * e];
        s_red[tid] = q;
        __syncthreads();
        for (int s = 64; s > 0; s >>= 1) {
            if (tid < s) s_red[tid] += s_red[tid + s];
            __syncthreads();
        }
        if (tid == 0) {
            out[0] = s_red[0] * 0.2390057361376673f;   // kJ/mol -> kcal/mol
            g_done = 0;                                 // reset for replay
        }
    }
}

// ---------------------------------------------------------------------------
extern "C" void kernel_launch(void* const* d_in, const int* in_sizes, int n_in,
                              void* d_out, int out_size) {
    const float* pos   = (const float*)d_in[0];
    const int*   types = (const int*)d_in[1];
    const float* emb   = (const float*)d_in[2];
    const float* W1    = (const float*)d_in[3];
    const float* w2    = (const float*)d_in[4];
    float*       out   = (float*)d_out;

    cudaFuncSetAttribute(k_mlp, cudaFuncAttributeMaxDynamicSharedMemorySize,
                         SMEM_MLP);

    k_wsplit      <<<256, 256>>>(W1);
    k_prep        <<<NA / 256, 256>>>(pos);
    k_scan_scatter<<<1, 1024>>>();
    k_sort        <<<(NCELL + 31) / 32, 32>>>();
    k_gather      <<<NA / 256, 256>>>(types);
    k_agg         <<<NCELL, 128>>>(emb);
    k_mlp         <<<NBLK, 128, SMEM_MLP>>>(w2, out);
}

// round 16
// speedup vs baseline: 1.6398x; 1.6398x over previous
#include <cuda_runtime.h>
#include <cuda_bf16.h>
#include <mma.h>
#include <cstdint>

using namespace nvcuda;

#define NA      8192
#define DD      128
#define HH      256
#define NC1     12          // cells per dimension (box 60 A / cutoff 5 A)
#define NCELL   (NC1*NC1*NC1)
#define MAXC    320         // max candidate atoms across 27 cells (mean ~128)
#define BMT     64          // mlp block tile M
#define BNT     64          // mlp block tile N
#define NBLK    ((NA/BMT)*(HH/BNT))   // 512 mlp blocks
#define LDS_AB  72          // padded smem leading dim (bf16)
#define LDS_AC  68          // padded epilogue leading dim (f32)

#define ABYTES   (64 * LDS_AB * 2)        // 9216 B per staged array
#define BUFBYTES (4 * ABYTES)             // 36864 B per kc buffer
#define SMEM_MLP (2 * BUFBYTES + 512 + 16)

typedef unsigned long long u64;

#define CP_ASYNC16(dst_u32, src_ptr) \
    asm volatile("cp.async.cg.shared.global [%0], [%1], 16;" \
                 :: "r"(dst_u32), "l"(src_ptr))
#define CP_COMMIT()  asm volatile("cp.async.commit_group;")
#define CP_WAIT0()   asm volatile("cp.async.wait_group 0;")

// ---- Scratch (static __device__ — no allocation) ---------------------------
__device__ float4        g_pos4[NA];
__device__ int           g_cellid[NA];
__device__ int           g_start[NCELL + 1];
__device__ int           g_slot[NA];       // cell-sorted original atom indices
__device__ float4        g_spos[NA];       // cell-sorted positions
__device__ int           g_stype[NA];      // cell-sorted types
__device__ __nv_bfloat16 g_Ahi[NA * HH];   // feat hi, row-major [8192][256]
__device__ __nv_bfloat16 g_Alo[NA * HH];   // feat lo
__device__ __nv_bfloat16 g_Bhi[HH * HH];   // W1 hi,  row-major [256][256]
__device__ __nv_bfloat16 g_Blo[HH * HH];   // W1 lo
__device__ float         g_partial[NBLK];
__device__ int           g_done = 0;

// bf16 two-term split: v ~= hi + lo, each bf16 (lo = rounding residual)
__device__ __forceinline__ void bf16_split(float v, __nv_bfloat16& h,
                                           __nv_bfloat16& l) {
    h = __float2bfloat16(v);
    l = __float2bfloat16(__fadd_rn(v, -__bfloat162float(h)));
}

__device__ __forceinline__ void store_split4(__nv_bfloat16* hi,
                                             __nv_bfloat16* lo, float4 v) {
    __nv_bfloat162 h01, h23, l01, l23;
    __nv_bfloat16 h, l;
    bf16_split(v.x, h, l); h01.x = h; l01.x = l;
    bf16_split(v.y, h, l); h01.y = h; l01.y = l;
    bf16_split(v.z, h, l); h23.x = h; l23.x = l;
    bf16_split(v.w, h, l); h23.y = h; l23.y = l;
    ((__nv_bfloat162*)hi)[0] = h01;
    ((__nv_bfloat162*)hi)[1] = h23;
    ((__nv_bfloat162*)lo)[0] = l01;
    ((__nv_bfloat162*)lo)[1] = l23;
}

// ---------------------------------------------------------------------------
// W1 bf16 split, row-major [K][N].
// ---------------------------------------------------------------------------
__global__ void k_wsplit(const float* __restrict__ W1) {
    int idx = blockIdx.x * 256 + threadIdx.x;     // 65536 total
    __nv_bfloat16 h, l;
    bf16_split(W1[idx], h, l);
    g_Bhi[idx] = h;
    g_Blo[idx] = l;
}

// ---------------------------------------------------------------------------
// Prep: nm -> angstrom; s = ((x*x)+(y*y))+(z*z) with NO fma contraction
// (matches XLA's elementwise/reduce rounding). Cell id only.
// ---------------------------------------------------------------------------
__global__ void k_prep(const float* __restrict__ pos) {
    int i = blockIdx.x * 256 + threadIdx.x;
    if (i < NA) {
        float x = __fmul_rn(10.0f, pos[3 * i + 0]);
        float y = __fmul_rn(10.0f, pos[3 * i + 1]);
        float z = __fmul_rn(10.0f, pos[3 * i + 2]);
        float s = __fadd_rn(__fadd_rn(__fmul_rn(x, x), __fmul_rn(y, y)),
                            __fmul_rn(z, z));
        g_pos4[i] = make_float4(x, y, z, s);
        int cx = min(NC1 - 1, max(0, (int)(x * 0.2f)));
        int cy = min(NC1 - 1, max(0, (int)(y * 0.2f)));
        int cz = min(NC1 - 1, max(0, (int)(z * 0.2f)));
        g_cellid[i] = (cz * NC1 + cy) * NC1 + cx;
    }
}

// ---------------------------------------------------------------------------
// Fused histogram + scan + scatter: one single-block kernel with SMEM
// counts/cursors (smem atomics ~32cyc vs ATOMG ~318cyc, no launch gaps).
// ---------------------------------------------------------------------------
__global__ void __launch_bounds__(1024) k_scan_scatter() {
    __shared__ int cnt[NCELL];
    __shared__ int cur[NCELL];
    __shared__ int a[2048], b[2048];
    const int t = threadIdx.x;

    cnt[t] = 0;
    if (t < NCELL - 1024) cnt[1024 + t] = 0;
    __syncthreads();

    int myc[8];
    #pragma unroll
    for (int k = 0; k < 8; k++) {
        myc[k] = g_cellid[t * 8 + k];
        atomicAdd(&cnt[myc[k]], 1);
    }
    __syncthreads();

    #pragma unroll
    for (int k = 0; k < 2; k++) {
        int idx = t + 1024 * k;
        a[idx] = (idx < NCELL) ? cnt[idx] : 0;
    }
    __syncthreads();
    int* src = a; int* dst = b;
    for (int s = 1; s < 2048; s <<= 1) {
        #pragma unroll
        for (int k = 0; k < 2; k++) {
            int idx = t + 1024 * k;
            int v = src[idx];
            if (idx >= s) v += src[idx - s];
            dst[idx] = v;
        }
        __syncthreads();
        int* tmp = src; src = dst; dst = tmp;
    }
    #pragma unroll
    for (int k = 0; k < 2; k++) {
        int idx = t + 1024 * k;
        if (idx < NCELL) {
            int st = src[idx] - cnt[idx];
            g_start[idx] = st;
            cur[idx]     = st;
        }
    }
    if (t == 0) g_start[NCELL] = NA;
    __syncthreads();

    #pragma unroll
    for (int k = 0; k < 8; k++) {
        int slot = atomicAdd(&cur[myc[k]], 1);
        g_slot[slot] = t * 8 + k;   // order arbitrary; warp sort restores
    }
}

// ---------------------------------------------------------------------------
// Warp-per-cell bitonic sort (registers + shfl, NO local memory) + gather.
// Lane i holds slot element i (INT_MAX pad); 15 shfl_xor compare-exchange
// steps sort 32 keys ascending; then lane-parallel gather of pos/type.
// Restores the exact deterministic ascending per-cell order.
// ---------------------------------------------------------------------------
__global__ void __launch_bounds__(128) k_sortgather(const int* __restrict__ types) {
    const int lane = threadIdx.x & 31;
    const int c    = blockIdx.x * 4 + (threadIdx.x >> 5);
    if (c >= NCELL) return;

    const int st = g_start[c];
    const int cn = g_start[c + 1] - st;

    int key = (lane < cn) ? g_slot[st + lane] : 0x7FFFFFFF;

    #pragma unroll
    for (int k = 2; k <= 32; k <<= 1) {
        #pragma unroll
        for (int j = k >> 1; j > 0; j >>= 1) {
            int other   = __shfl_xor_sync(0xffffffffu, key, j);
            bool up     = ((lane & k) == 0);     // ascending region
            bool lower  = ((lane & j) == 0);
            key = (up == lower) ? min(key, other) : max(key, other);
        }
    }

    if (lane < cn) {
        g_slot[st + lane]  = key;
        g_spos[st + lane]  = g_pos4[key];
        g_stype[st + lane] = types[key];
    }
}

// ---------------------------------------------------------------------------
// Per-CELL radius graph + aggregation, warp-independent home atoms.
// d2 <= 25.01f prefilter (provably includes all reference-acceptable pairs;
// exact test still applied inside). Pair math bit-exact vs reference:
//   dot = fma(z,z, fma(y,y, x*x));  d2 = RN(RN(s_i+s_j) - 2*dot)
// ---------------------------------------------------------------------------
__global__ void __launch_bounds__(128) k_agg(const float* __restrict__ emb) {
    __shared__ float4        s_cpos[MAXC];
    __shared__ int           s_ctyp[MAXC];
    __shared__ unsigned char s_cmap[MAXC];
    __shared__ int           s_gst[32];
    __shared__ int           s_coff[33];

    const int tl   = threadIdx.x;
    const int lane = tl & 31, w = tl >> 5;
    const int c  = blockIdx.x;
    const int cx = c % NC1, cy = (c / NC1) % NC1, cz = c / (NC1 * NC1);

    if (tl < 32) {
        int st = 0, cnt = 0;
        if (tl < 27) {
            int nx = cx + tl % 3 - 1;
            int ny = cy + (tl / 3) % 3 - 1;
            int nz = cz + tl / 9 - 1;
            if (nx >= 0 && nx < NC1 && ny >= 0 && ny < NC1 &&
                nz >= 0 && nz < NC1) {
                int nc = (nz * NC1 + ny) * NC1 + nx;
                st  = g_start[nc];
                cnt = g_start[nc + 1] - st;
            }
        }
        s_gst[tl] = st;
        int v = cnt;
        #pragma unroll
        for (int o = 1; o < 32; o <<= 1) {
            int u2 = __shfl_up_sync(0xffffffffu, v, o);
            if (lane >= o) v += u2;
        }
        s_coff[tl + 1] = v;
        if (tl == 0) s_coff[0] = 0;
        int off = v - cnt;
        for (int q = 0; q < cnt; q++)
            s_cmap[off + q] = (unsigned char)tl;
    }
    __syncthreads();

    const int ncand = s_coff[27];
    const int hbase = s_coff[13];
    const int nhome = s_coff[14] - s_coff[13];
    const int hst   = s_gst[13];
    if (nhome == 0) return;

    for (int p = tl; p < ncand; p += 128) {
        int q    = s_cmap[p];
        int slot = s_gst[q] + (p - s_coff[q]);
        s_cpos[p] = g_spos[slot];
        s_ctyp[p] = g_stype[slot];
    }
    __syncthreads();

    for (int ha = w; ha < nhome; ha += 4) {
        const float4 pi = s_cpos[hbase + ha];
        float4 acc = make_float4(0.f, 0.f, 0.f, 0.f);

        for (int base = 0; base < ncand; base += 32) {
            int k = base + lane;
            int pred = 0, typ = 0;
            float phi = 0.0f;
            if (k < ncand) {
                float4 pj = s_cpos[k];
                float dot = __fmul_rn(pi.x, pj.x);
                dot = fmaf(pi.y, pj.y, dot);
                dot = fmaf(pi.z, pj.z, dot);
                float t1 = __fadd_rn(pi.w, pj.w);
                float d2 = __fadd_rn(t1, __fmul_rn(-2.0f, dot));
                if (d2 > 1e-12f && d2 <= 25.01f) {       // cheap prefilter
                    float d = __fsqrt_rn(d2);
                    if (d <= 5.0f) {                      // exact ref test
                        pred = 1; phi = expf(-d); typ = s_ctyp[k];
                    }
                }
            }
            unsigned m = __ballot_sync(0xffffffffu, pred);
            while (m) {                          // ascending lane = cand order
                int srcl = __ffs(m) - 1;
                m &= m - 1;
                float ph = __shfl_sync(0xffffffffu, phi, srcl);
                int   ty = __shfl_sync(0xffffffffu, typ, srcl);
                float4 ev = *(const float4*)(emb + ty * DD + lane * 4);
                acc.x = fmaf(ph, ev.x, acc.x);
                acc.y = fmaf(ph, ev.y, acc.y);
                acc.z = fmaf(ph, ev.z, acc.z);
                acc.w = fmaf(ph, ev.w, acc.w);
            }
        }

        const int i  = g_slot[hst + ha];         // original atom index
        const int ti = s_ctyp[hbase + ha];
        float4 hv = *(const float4*)(emb + ti * DD + lane * 4);
        store_split4(g_Ahi + (u64)i * HH + lane * 4,
                     g_Alo + (u64)i * HH + lane * 4, hv);
        store_split4(g_Ahi + (u64)i * HH + 128 + lane * 4,
                     g_Alo + (u64)i * HH + 128 + lane * 4, acc);
    }
}

// ---------------------------------------------------------------------------
// MLP on wmma bf16 two-term split GEMM, cp.async double-buffered staging
// (unchanged from round 13 — known good).
// ---------------------------------------------------------------------------
__global__ void __launch_bounds__(128) k_mlp(const float* __restrict__ w2,
                                             float* __restrict__ out) {
    extern __shared__ __align__(16) char smem_dyn[];
    float* s_acc  = (float*)smem_dyn;             // reused after mainloop
    float* s_red  = (float*)(smem_dyn + 2 * BUFBYTES);
    int*   s_last = (int*)(smem_dyn + 2 * BUFBYTES + 512);

    const int tid  = threadIdx.x;
    const int wid  = tid >> 5;
    const int wm   = wid & 1, wn = wid >> 1;
    const int mt   = blockIdx.x >> 2, nt = blockIdx.x & 3;
    const int m0   = mt * BMT, n0 = nt * BNT;

    uint32_t sb;
    asm("{ .reg .u64 t; cvta.to.shared.u64 t, %1; cvt.u32.u64 %0, t; }"
        : "=r"(sb) : "l"(smem_dyn));

    auto stage = [&](int kc, int buf) {
        uint32_t dbase = sb + buf * BUFBYTES;
        #pragma unroll
        for (int q = 0; q < 4; q++) {
            int j = tid + 128 * q;
            int row = j >> 3, c8 = j & 7;
            uint32_t doff = dbase + row * (LDS_AB * 2) + c8 * 16;
            const char* sa = (const char*)(g_Ahi + (u64)(m0 + row) * HH + kc * 64) + c8 * 16;
            const char* sl = (const char*)(g_Alo + (u64)(m0 + row) * HH + kc * 64) + c8 * 16;
            const char* sh = (const char*)(g_Bhi + (u64)(kc * 64 + row) * HH + n0) + c8 * 16;
            const char* sw = (const char*)(g_Blo + (u64)(kc * 64 + row) * HH + n0) + c8 * 16;
            CP_ASYNC16(doff + 0 * ABYTES, sa);
            CP_ASYNC16(doff + 1 * ABYTES, sl);
            CP_ASYNC16(doff + 2 * ABYTES, sh);
            CP_ASYNC16(doff + 3 * ABYTES, sw);
        }
        CP_COMMIT();
    };

    wmma::fragment<wmma::accumulator, 16, 16, 16, float> acc[2][2];
    #pragma unroll
    for (int i = 0; i < 2; i++)
        #pragma unroll
        for (int j = 0; j < 2; j++)
            wmma::fill_fragment(acc[i][j], 0.0f);

    stage(0, 0);

    #pragma unroll 1
    for (int kc = 0; kc < 4; kc++) {
        CP_WAIT0();
        __syncthreads();                 // data landed; prior buf free
        if (kc < 3) stage(kc + 1, (kc + 1) & 1);

        const char* bufp = smem_dyn + (kc & 1) * BUFBYTES;
        const __nv_bfloat16* sAhi = (const __nv_bfloat16*)(bufp + 0 * ABYTES);
        const __nv_bfloat16* sAlo = (const __nv_bfloat16*)(bufp + 1 * ABYTES);
        const __nv_bfloat16* sBhi = (const __nv_bfloat16*)(bufp + 2 * ABYTES);
        const __nv_bfloat16* sBlo = (const __nv_bfloat16*)(bufp + 3 * ABYTES);

        #pragma unroll
        for (int sp = 0; sp < 3; sp++) {          // hi*hi, hi*lo, lo*hi
            const __nv_bfloat16* sA = (sp == 2) ? sAlo : sAhi;
            const __nv_bfloat16* sB = (sp == 1) ? sBlo : sBhi;
            #pragma unroll
            for (int ks = 0; ks < 4; ks++) {
                wmma::fragment<wmma::matrix_a, 16, 16, 16, __nv_bfloat16,
                               wmma::row_major> af[2];
                wmma::fragment<wmma::matrix_b, 16, 16, 16, __nv_bfloat16,
                               wmma::row_major> bf[2];
                #pragma unroll
                for (int i = 0; i < 2; i++)
                    wmma::load_matrix_sync(
                        af[i], sA + (wm * 32 + i * 16) * LDS_AB + ks * 16,
                        LDS_AB);
                #pragma unroll
                for (int j = 0; j < 2; j++)
                    wmma::load_matrix_sync(
                        bf[j], sB + (ks * 16) * LDS_AB + wn * 32 + j * 16,
                        LDS_AB);
                #pragma unroll
                for (int i = 0; i < 2; i++)
                    #pragma unroll
                    for (int j = 0; j < 2; j++)
                        wmma::mma_sync(acc[i][j], af[i], bf[j], acc[i][j]);
            }
        }
    }
    __syncthreads();

    #pragma unroll
    for (int i = 0; i < 2; i++)
        #pragma unroll
        for (int j = 0; j < 2; j++)
            wmma::store_matrix_sync(
                s_acc + (wm * 32 + i * 16) * LDS_AC + wn * 32 + j * 16,
                acc[i][j], LDS_AC, wmma::mem_row_major);
    __syncthreads();

    float p = 0.0f;
    #pragma unroll
    for (int e = 0; e < 32; e++) {
        int idx = tid + 128 * e;
        int row = idx >> 6, col = idx & 63;
        p += fmaxf(s_acc[row * LDS_AC + col], 0.0f) * __ldg(w2 + n0 + col);
    }
    s_red[tid] = p;
    __syncthreads();
    for (int s = 64; s > 0; s >>= 1) {
        if (tid < s) s_red[tid] += s_red[tid + s];
        __syncthreads();
    }
    if (tid == 0) g_partial[blockIdx.x] = s_red[0];

    __threadfence();
    if (tid == 0) *s_last = (atomicAdd(&g_done, 1) == gridDim.x - 1);
    __syncthreads();
    if (*s_last) {
        __threadfence();
        volatile float* gp = (volatile float*)g_partial;
        float q = 0.0f;
        #pragma unroll
        for (int e = 0; e < 4; e++) q += gp[tid + 128 * e];
        s_red[tid] = q;
        __syncthreads();
        for (int s = 64; s > 0; s >>= 1) {
            if (tid < s) s_red[tid] += s_red[tid + s];
            __syncthreads();
        }
        if (tid == 0) {
            out[0] = s_red[0] * 0.2390057361376673f;   // kJ/mol -> kcal/mol
            g_done = 0;                                 // reset for replay
        }
    }
}

// ---------------------------------------------------------------------------
extern "C" void kernel_launch(void* const* d_in, const int* in_sizes, int n_in,
                              void* d_out, int out_size) {
    const float* pos   = (const float*)d_in[0];
    const int*   types = (const int*)d_in[1];
    const float* emb   = (const float*)d_in[2];
    const float* W1    = (const float*)d_in[3];
    const float* w2    = (const float*)d_in[4];
    float*       out   = (float*)d_out;

    cudaFuncSetAttribute(k_mlp, cudaFuncAttributeMaxDynamicSharedMemorySize,
                         SMEM_MLP);

    k_wsplit      <<<256, 256>>>(W1);
    k_prep        <<<NA / 256, 256>>>(pos);
    k_scan_scatter<<<1, 1024>>>();
    k_sortgather  <<<(NCELL + 3) / 4, 128>>>(types);
    k_agg         <<<NCELL, 128>>>(emb);
    k_mlp         <<<NBLK, 128, SMEM_MLP>>>(w2, out);
}

// round 17
// speedup vs baseline: 1.7744x; 1.0821x over previous
#include <cuda_runtime.h>
#include <cuda_bf16.h>
#include <mma.h>
#include <cstdint>

using namespace nvcuda;

#define NA      8192
#define DD      128
#define HH      256
#define NC1     12          // cells per dimension (box 60 A / cutoff 5 A)
#define NCELL   (NC1*NC1*NC1)
#define MAXC    320         // max candidate atoms across 27 cells (mean ~128)
#define BMT     128         // mlp block tile M
#define BNT     64          // mlp block tile N
#define NBLK    ((NA/BMT)*(HH/BNT))   // 64*4 = 256 mlp blocks
#define LDS_AB  72          // padded smem leading dim (bf16)
#define LDS_AC  68          // padded epilogue leading dim (f32)

#define ABYTES_A (BMT * LDS_AB * 2)       // 18432 B per staged A array
#define ABYTES_B (BNT * LDS_AB * 2)       //  9216 B per staged B array
#define BUFBYTES (2 * ABYTES_A + 2 * ABYTES_B)   // 55296 B per kc buffer
#define SMEM_MLP (2 * BUFBYTES + 1024 + 16)      // ~111.6 KB -> 2 blocks/SM

typedef unsigned long long u64;

#define CP_ASYNC16(dst_u32, src_ptr) \
    asm volatile("cp.async.cg.shared.global [%0], [%1], 16;" \
                 :: "r"(dst_u32), "l"(src_ptr))
#define CP_COMMIT()  asm volatile("cp.async.commit_group;")
#define CP_WAIT0()   asm volatile("cp.async.wait_group 0;")

// ---- Scratch (static __device__ — no allocation) ---------------------------
__device__ float4        g_pos4[NA];
__device__ int           g_cellid[NA];
__device__ int           g_start[NCELL + 1];
__device__ int           g_slot[NA];       // cell-sorted original atom indices
__device__ float4        g_spos[NA];       // cell-sorted positions
__device__ int           g_stype[NA];      // cell-sorted types
__device__ __nv_bfloat16 g_Ahi[NA * HH];   // feat hi, row-major [8192][256]
__device__ __nv_bfloat16 g_Alo[NA * HH];   // feat lo
__device__ __nv_bfloat16 g_Bhi[HH * HH];   // W1 hi,  row-major [256][256]
__device__ __nv_bfloat16 g_Blo[HH * HH];   // W1 lo
__device__ float         g_partial[NBLK];
__device__ int           g_done = 0;

// bf16 two-term split: v ~= hi + lo, each bf16 (lo = rounding residual)
__device__ __forceinline__ void bf16_split(float v, __nv_bfloat16& h,
                                           __nv_bfloat16& l) {
    h = __float2bfloat16(v);
    l = __float2bfloat16(__fadd_rn(v, -__bfloat162float(h)));
}

__device__ __forceinline__ void store_split4(__nv_bfloat16* hi,
                                             __nv_bfloat16* lo, float4 v) {
    __nv_bfloat162 h01, h23, l01, l23;
    __nv_bfloat16 h, l;
    bf16_split(v.x, h, l); h01.x = h; l01.x = l;
    bf16_split(v.y, h, l); h01.y = h; l01.y = l;
    bf16_split(v.z, h, l); h23.x = h; l23.x = l;
    bf16_split(v.w, h, l); h23.y = h; l23.y = l;
    ((__nv_bfloat162*)hi)[0] = h01;
    ((__nv_bfloat162*)hi)[1] = h23;
    ((__nv_bfloat162*)lo)[0] = l01;
    ((__nv_bfloat162*)lo)[1] = l23;
}

// ---------------------------------------------------------------------------
// Fused prep + W1 split. Blocks 0-31: position prep (nm -> angstrom,
// s = ((x*x)+(y*y))+(z*z), NO fma contraction — matches XLA rounding) +
// cell id. Blocks 32-287: W1 bf16 split.
// ---------------------------------------------------------------------------
__global__ void k_prep_wsplit(const float* __restrict__ pos,
                              const float* __restrict__ W1) {
    const int b = blockIdx.x;
    if (b < 32) {
        int i = b * 256 + threadIdx.x;
        float x = __fmul_rn(10.0f, pos[3 * i + 0]);
        float y = __fmul_rn(10.0f, pos[3 * i + 1]);
        float z = __fmul_rn(10.0f, pos[3 * i + 2]);
        float s = __fadd_rn(__fadd_rn(__fmul_rn(x, x), __fmul_rn(y, y)),
                            __fmul_rn(z, z));
        g_pos4[i] = make_float4(x, y, z, s);
        int cx = min(NC1 - 1, max(0, (int)(x * 0.2f)));
        int cy = min(NC1 - 1, max(0, (int)(y * 0.2f)));
        int cz = min(NC1 - 1, max(0, (int)(z * 0.2f)));
        g_cellid[i] = (cz * NC1 + cy) * NC1 + cx;
    } else {
        int idx = (b - 32) * 256 + threadIdx.x;   // 65536 total
        __nv_bfloat16 h, l;
        bf16_split(W1[idx], h, l);
        g_Bhi[idx] = h;
        g_Blo[idx] = l;
    }
}

// ---------------------------------------------------------------------------
// Fused histogram + scan + scatter: one single-block kernel with SMEM
// counts/cursors (smem atomics ~32cyc vs ATOMG ~318cyc, no launch gaps).
// ---------------------------------------------------------------------------
__global__ void __launch_bounds__(1024) k_scan_scatter() {
    __shared__ int cnt[NCELL];
    __shared__ int cur[NCELL];
    __shared__ int a[2048], b[2048];
    const int t = threadIdx.x;

    cnt[t] = 0;
    if (t < NCELL - 1024) cnt[1024 + t] = 0;
    __syncthreads();

    int myc[8];
    #pragma unroll
    for (int k = 0; k < 8; k++) {
        myc[k] = g_cellid[t * 8 + k];
        atomicAdd(&cnt[myc[k]], 1);
    }
    __syncthreads();

    #pragma unroll
    for (int k = 0; k < 2; k++) {
        int idx = t + 1024 * k;
        a[idx] = (idx < NCELL) ? cnt[idx] : 0;
    }
    __syncthreads();
    int* src = a; int* dst = b;
    for (int s = 1; s < 2048; s <<= 1) {
        #pragma unroll
        for (int k = 0; k < 2; k++) {
            int idx = t + 1024 * k;
            int v = src[idx];
            if (idx >= s) v += src[idx - s];
            dst[idx] = v;
        }
        __syncthreads();
        int* tmp = src; src = dst; dst = tmp;
    }
    #pragma unroll
    for (int k = 0; k < 2; k++) {
        int idx = t + 1024 * k;
        if (idx < NCELL) {
            int st = src[idx] - cnt[idx];
            g_start[idx] = st;
            cur[idx]     = st;
        }
    }
    if (t == 0) g_start[NCELL] = NA;
    __syncthreads();

    #pragma unroll
    for (int k = 0; k < 8; k++) {
        int slot = atomicAdd(&cur[myc[k]], 1);
        g_slot[slot] = t * 8 + k;   // order arbitrary; warp sort restores
    }
}

// ---------------------------------------------------------------------------
// Warp-per-cell bitonic sort (registers + shfl, NO local memory) + gather.
// Restores the exact deterministic ascending per-cell order.
// ---------------------------------------------------------------------------
__global__ void __launch_bounds__(128) k_sortgather(const int* __restrict__ types) {
    const int lane = threadIdx.x & 31;
    const int c    = blockIdx.x * 4 + (threadIdx.x >> 5);
    if (c >= NCELL) return;

    const int st = g_start[c];
    const int cn = g_start[c + 1] - st;

    int key = (lane < cn) ? g_slot[st + lane] : 0x7FFFFFFF;

    #pragma unroll
    for (int k = 2; k <= 32; k <<= 1) {
        #pragma unroll
        for (int j = k >> 1; j > 0; j >>= 1) {
            int other   = __shfl_xor_sync(0xffffffffu, key, j);
            bool up     = ((lane & k) == 0);
            bool lower  = ((lane & j) == 0);
            key = (up == lower) ? min(key, other) : max(key, other);
        }
    }

    if (lane < cn) {
        g_slot[st + lane]  = key;
        g_spos[st + lane]  = g_pos4[key];
        g_stype[st + lane] = types[key];
    }
}

// ---------------------------------------------------------------------------
// Per-CELL radius graph + aggregation, warp-independent home atoms.
// d2 <= 25.01f prefilter (provably includes all reference-acceptable pairs;
// exact test still applied inside). Pair math bit-exact vs reference:
//   dot = fma(z,z, fma(y,y, x*x));  d2 = RN(RN(s_i+s_j) - 2*dot)
// ---------------------------------------------------------------------------
__global__ void __launch_bounds__(128) k_agg(const float* __restrict__ emb) {
    __shared__ float4        s_cpos[MAXC];
    __shared__ int           s_ctyp[MAXC];
    __shared__ unsigned char s_cmap[MAXC];
    __shared__ int           s_gst[32];
    __shared__ int           s_coff[33];

    const int tl   = threadIdx.x;
    const int lane = tl & 31, w = tl >> 5;
    const int c  = blockIdx.x;
    const int cx = c % NC1, cy = (c / NC1) % NC1, cz = c / (NC1 * NC1);

    if (tl < 32) {
        int st = 0, cnt = 0;
        if (tl < 27) {
            int nx = cx + tl % 3 - 1;
            int ny = cy + (tl / 3) % 3 - 1;
            int nz = cz + tl / 9 - 1;
            if (nx >= 0 && nx < NC1 && ny >= 0 && ny < NC1 &&
                nz >= 0 && nz < NC1) {
                int nc = (nz * NC1 + ny) * NC1 + nx;
                st  = g_start[nc];
                cnt = g_start[nc + 1] - st;
            }
        }
        s_gst[tl] = st;
        int v = cnt;
        #pragma unroll
        for (int o = 1; o < 32; o <<= 1) {
            int u2 = __shfl_up_sync(0xffffffffu, v, o);
            if (lane >= o) v += u2;
        }
        s_coff[tl + 1] = v;
        if (tl == 0) s_coff[0] = 0;
        int off = v - cnt;
        for (int q = 0; q < cnt; q++)
            s_cmap[off + q] = (unsigned char)tl;
    }
    __syncthreads();

    const int ncand = s_coff[27];
    const int hbase = s_coff[13];
    const int nhome = s_coff[14] - s_coff[13];
    const int hst   = s_gst[13];
    if (nhome == 0) return;

    for (int p = tl; p < ncand; p += 128) {
        int q    = s_cmap[p];
        int slot = s_gst[q] + (p - s_coff[q]);
        s_cpos[p] = g_spos[slot];
        s_ctyp[p] = g_stype[slot];
    }
    __syncthreads();

    for (int ha = w; ha < nhome; ha += 4) {
        const float4 pi = s_cpos[hbase + ha];
        float4 acc = make_float4(0.f, 0.f, 0.f, 0.f);

        for (int base = 0; base < ncand; base += 32) {
            int k = base + lane;
            int pred = 0, typ = 0;
            float phi = 0.0f;
            if (k < ncand) {
                float4 pj = s_cpos[k];
                float dot = __fmul_rn(pi.x, pj.x);
                dot = fmaf(pi.y, pj.y, dot);
                dot = fmaf(pi.z, pj.z, dot);
                float t1 = __fadd_rn(pi.w, pj.w);
                float d2 = __fadd_rn(t1, __fmul_rn(-2.0f, dot));
                if (d2 > 1e-12f && d2 <= 25.01f) {       // cheap prefilter
                    float d = __fsqrt_rn(d2);
                    if (d <= 5.0f) {                      // exact ref test
                        pred = 1; phi = expf(-d); typ = s_ctyp[k];
                    }
                }
            }
            unsigned m = __ballot_sync(0xffffffffu, pred);
            while (m) {                          // ascending lane = cand order
                int srcl = __ffs(m) - 1;
                m &= m - 1;
                float ph = __shfl_sync(0xffffffffu, phi, srcl);
                int   ty = __shfl_sync(0xffffffffu, typ, srcl);
                float4 ev = *(const float4*)(emb + ty * DD + lane * 4);
                acc.x = fmaf(ph, ev.x, acc.x);
                acc.y = fmaf(ph, ev.y, acc.y);
                acc.z = fmaf(ph, ev.z, acc.z);
                acc.w = fmaf(ph, ev.w, acc.w);
            }
        }

        const int i  = g_slot[hst + ha];         // original atom index
        const int ti = s_ctyp[hbase + ha];
        float4 hv = *(const float4*)(emb + ti * DD + lane * 4);
        store_split4(g_Ahi + (u64)i * HH + lane * 4,
                     g_Alo + (u64)i * HH + lane * 4, hv);
        store_split4(g_Ahi + (u64)i * HH + 128 + lane * 4,
                     g_Alo + (u64)i * HH + 128 + lane * 4, acc);
    }
}

// ---------------------------------------------------------------------------
// MLP on wmma bf16 two-term split GEMM. Retiled for occupancy: 128x64 block
// tile, 256 threads (8 warps, 4x2 warp grid, 32x32 warp tiles), cp.async
// double-buffered kc chunks — ~111.6 KB smem -> 2 blocks/SM = 16 warps/SM
// (vs 4 before), 4x the SMSP latency hiding.
// ---------------------------------------------------------------------------
__global__ void __launch_bounds__(256, 2) k_mlp(const float* __restrict__ w2,
                                                float* __restrict__ out) {
    extern __shared__ __align__(16) char smem_dyn[];
    float* s_acc  = (float*)smem_dyn;             // reused after mainloop
    float* s_red  = (float*)(smem_dyn + 2 * BUFBYTES);
    int*   s_last = (int*)(smem_dyn + 2 * BUFBYTES + 1024);

    const int tid  = threadIdx.x;
    const int wid  = tid >> 5;
    const int wm   = wid & 3, wn = wid >> 2;      // 4x2 warp grid
    const int mt   = blockIdx.x >> 2, nt = blockIdx.x & 3;
    const int m0   = mt * BMT, n0 = nt * BNT;

    uint32_t sb;
    asm("{ .reg .u64 t; cvta.to.shared.u64 t, %1; cvt.u32.u64 %0, t; }"
        : "=r"(sb) : "l"(smem_dyn));

    // buffer layout: [Ahi 18432][Alo 18432][Bhi 9216][Blo 9216]
    auto stage = [&](int kc, int buf) {
        uint32_t dbase = sb + buf * BUFBYTES;
        #pragma unroll
        for (int q = 0; q < 4; q++) {             // A: 1024 uint4 per array
            int j = tid + 256 * q;
            int row = j >> 3, c8 = j & 7;
            uint32_t doff = dbase + row * (LDS_AB * 2) + c8 * 16;
            const char* sa = (const char*)(g_Ahi + (u64)(m0 + row) * HH + kc * 64) + c8 * 16;
            const char* sl = (const char*)(g_Alo + (u64)(m0 + row) * HH + kc * 64) + c8 * 16;
            CP_ASYNC16(doff,            sa);
            CP_ASYNC16(doff + ABYTES_A, sl);
        }
        #pragma unroll
        for (int q = 0; q < 2; q++) {             // B: 512 uint4 per array
            int j = tid + 256 * q;
            int row = j >> 3, c8 = j & 7;
            uint32_t doff = dbase + 2 * ABYTES_A + row * (LDS_AB * 2) + c8 * 16;
            const char* sh = (const char*)(g_Bhi + (u64)(kc * 64 + row) * HH + n0) + c8 * 16;
            const char* sw = (const char*)(g_Blo + (u64)(kc * 64 + row) * HH + n0) + c8 * 16;
            CP_ASYNC16(doff,            sh);
            CP_ASYNC16(doff + ABYTES_B, sw);
        }
        CP_COMMIT();
    };

    wmma::fragment<wmma::accumulator, 16, 16, 16, float> acc[2][2];
    #pragma unroll
    for (int i = 0; i < 2; i++)
        #pragma unroll
        for (int j = 0; j < 2; j++)
            wmma::fill_fragment(acc[i][j], 0.0f);

    stage(0, 0);

    #pragma unroll 1
    for (int kc = 0; kc < 4; kc++) {
        CP_WAIT0();
        __syncthreads();                 // data landed; prior buf free
        if (kc < 3) stage(kc + 1, (kc + 1) & 1);

        const char* bufp = smem_dyn + (kc & 1) * BUFBYTES;
        const __nv_bfloat16* sAhi = (const __nv_bfloat16*)(bufp);
        const __nv_bfloat16* sAlo = (const __nv_bfloat16*)(bufp + ABYTES_A);
        const __nv_bfloat16* sBhi = (const __nv_bfloat16*)(bufp + 2 * ABYTES_A);
        const __nv_bfloat16* sBlo = (const __nv_bfloat16*)(bufp + 2 * ABYTES_A + ABYTES_B);

        #pragma unroll
        for (int sp = 0; sp < 3; sp++) {          // hi*hi, hi*lo, lo*hi
            const __nv_bfloat16* sA = (sp == 2) ? sAlo : sAhi;
            const __nv_bfloat16* sB = (sp == 1) ? sBlo : sBhi;
            #pragma unroll
            for (int ks = 0; ks < 4; ks++) {
                wmma::fragment<wmma::matrix_a, 16, 16, 16, __nv_bfloat16,
                               wmma::row_major> af[2];
                wmma::fragment<wmma::matrix_b, 16, 16, 16, __nv_bfloat16,
                               wmma::row_major> bf[2];
                #pragma unroll
                for (int i = 0; i < 2; i++)
                    wmma::load_matrix_sync(
                        af[i], sA + (wm * 32 + i * 16) * LDS_AB + ks * 16,
                        LDS_AB);
                #pragma unroll
                for (int j = 0; j < 2; j++)
                    wmma::load_matrix_sync(
                        bf[j], sB + (ks * 16) * LDS_AB + wn * 32 + j * 16,
                        LDS_AB);
                #pragma unroll
                for (int i = 0; i < 2; i++)
                    #pragma unroll
                    for (int j = 0; j < 2; j++)
                        wmma::mma_sync(acc[i][j], af[i], bf[j], acc[i][j]);
            }
        }
    }
    __syncthreads();

    #pragma unroll
    for (int i = 0; i < 2; i++)
        #pragma unroll
        for (int j = 0; j < 2; j++)
            wmma::store_matrix_sync(
                s_acc + (wm * 32 + i * 16) * LDS_AC + wn * 32 + j * 16,
                acc[i][j], LDS_AC, wmma::mem_row_major);
    __syncthreads();

    float p = 0.0f;
    #pragma unroll
    for (int e = 0; e < 32; e++) {                // 128x64 elements / 256 thr
        int idx = tid + 256 * e;
        int row = idx >> 6, col = idx & 63;
        p += fmaxf(s_acc[row * LDS_AC + col], 0.0f) * __ldg(w2 + n0 + col);
    }
    s_red[tid] = p;
    __syncthreads();
    for (int s = 128; s > 0; s >>= 1) {
        if (tid < s) s_red[tid] += s_red[tid + s];
        __syncthreads();
    }
    if (tid == 0) g_partial[blockIdx.x] = s_red[0];

    __threadfence();
    if (tid == 0) *s_last = (atomicAdd(&g_done, 1) == gridDim.x - 1);
    __syncthreads();
    if (*s_last) {
        __threadfence();
        volatile float* gp = (volatile float*)g_partial;
        s_red[tid] = gp[tid];                      // NBLK == 256
        __syncthreads();
        for (int s = 128; s > 0; s >>= 1) {
            if (tid < s) s_red[tid] += s_red[tid + s];
            __syncthreads();
        }
        if (tid == 0) {
            out[0] = s_red[0] * 0.2390057361376673f;   // kJ/mol -> kcal/mol
            g_done = 0;                                 // reset for replay
        }
    }
}

// ---------------------------------------------------------------------------
extern "C" void kernel_launch(void* const* d_in, const int* in_sizes, int n_in,
                              void* d_out, int out_size) {
    const float* pos   = (const float*)d_in[0];
    const int*   types = (const int*)d_in[1];
    const float* emb   = (const float*)d_in[2];
    const float* W1    = (const float*)d_in[3];
    const float* w2    = (const float*)d_in[4];
    float*       out   = (float*)d_out;

    cudaFuncSetAttribute(k_mlp, cudaFuncAttributeMaxDynamicSharedMemorySize,
                         SMEM_MLP);

    k_prep_wsplit <<<288, 256>>>(pos, W1);
    k_scan_scatter<<<1, 1024>>>();
    k_sortgather  <<<(NCELL + 3) / 4, 128>>>(types);
    k_agg         <<<NCELL, 128>>>(emb);
    k_mlp         <<<NBLK, 256, SMEM_MLP>>>(w2, out);
}